// round 15
// baseline (speedup 1.0000x reference)
#include <cuda_runtime.h>
#include <cuda_fp16.h>
#include <cfloat>
#include <cstdint>

// Problem constants
#define BQ    2048
#define NB    50000
#define NBP   50048     // 391*128
#define DIM   128
#define TOPK  20
#define NCAND 64
#define NGRP  1564      // NBP / 32
#define NGRPP 1568      // padded to 8*196

// quantization scales
#define QA1   (127.0f / 12.0f)   // p1 queries (2z, clamp +-12)
#define QB1   (127.0f / 6.0f)    // p1 books   (clamp +-6)
#define INV0  (1.0f / (127.0f * 127.0f))
#define INV1  ((12.0f * 6.0f) / (127.0f * 127.0f))

// ======================= device scratch ====================================
__device__ float  g_zq[BQ];
__device__ float  g_bq[NBP];
__device__ float  g_qf[2 * BQ * DIM];
__device__ signed char g_qa8[2 * BQ * DIM];
__device__ signed char g_ba8[(size_t)2 * NBP * DIM];
__device__ uint4  g_s16v[(size_t)2 * BQ * NBP / 8];   // approx scores fp16
__device__ __half g_gmax[(size_t)2 * BQ * NGRPP];     // per-32 group maxes

// ======================= helpers ===========================================
__device__ __forceinline__ uint32_t smem_u32(const void* p) {
    uint32_t a;
    asm("{ .reg .u64 t; cvta.to.shared.u64 t, %1; cvt.u32.u64 %0, t; }" : "=r"(a) : "l"(p));
    return a;
}
__device__ __forceinline__ void ldsm_x4(uint32_t addr, uint32_t* r) {
    asm volatile("ldmatrix.sync.aligned.m8n8.x4.shared.b16 {%0,%1,%2,%3}, [%4];"
        : "=r"(r[0]), "=r"(r[1]), "=r"(r[2]), "=r"(r[3]) : "r"(addr));
}
// int8 IMMA: m16n8k32 s32 accum
__device__ __forceinline__ void mma16832s8(int* d, const uint32_t* a, const uint32_t* b) {
    asm volatile("mma.sync.aligned.m16n8k32.row.col.s32.s8.s8.s32 "
        "{%0,%1,%2,%3}, {%4,%5,%6,%7}, {%8,%9}, {%0,%1,%2,%3};"
        : "+r"(d[0]), "+r"(d[1]), "+r"(d[2]), "+r"(d[3])
        : "r"(a[0]), "r"(a[1]), "r"(a[2]), "r"(a[3]), "r"(b[0]), "r"(b[1]));
}
// order-preserving transform: half bits (16) -> uint16 with integer order
__device__ __forceinline__ unsigned int h2ord(unsigned int u) {
    return u ^ (0x8000u | (0x7FFFu & (0u - (u >> 15))));
}
__device__ __forceinline__ signed char q8(float x, float sc) {
    float v = fminf(fmaxf(x * sc, -127.0f), 127.0f);
    return (signed char)__float2int_rn(v);
}

// ======================= prep kernels ======================================
__global__ void prep_queries(const float* __restrict__ z_rot,
                             const float* __restrict__ z_trans) {
    int warp = (blockIdx.x * blockDim.x + threadIdx.x) >> 5;
    int lane = threadIdx.x & 31;
    if (warp >= BQ) return;

    float4 v = reinterpret_cast<const float4*>(z_rot + (size_t)warp * DIM)[lane];
    float s = v.x * v.x + v.y * v.y + v.z * v.z + v.w * v.w;
    #pragma unroll
    for (int o = 16; o; o >>= 1) s += __shfl_xor_sync(0xFFFFFFFFu, s, o);
    float inv = 1.0f / sqrtf(s);
    float rv[4] = {v.x * inv, v.y * inv, v.z * inv, v.w * inv};
    size_t base0 = (size_t)warp * DIM + lane * 4;
    #pragma unroll
    for (int j = 0; j < 4; j++) {
        g_qf[base0 + j]  = rv[j];
        g_qa8[base0 + j] = q8(rv[j], 127.0f);
    }

    float4 t = reinterpret_cast<const float4*>(z_trans + (size_t)warp * DIM)[lane];
    float sq = t.x * t.x + t.y * t.y + t.z * t.z + t.w * t.w;
    #pragma unroll
    for (int o = 16; o; o >>= 1) sq += __shfl_xor_sync(0xFFFFFFFFu, sq, o);
    float tv[4] = {2.0f * t.x, 2.0f * t.y, 2.0f * t.z, 2.0f * t.w};
    size_t base1 = (size_t)(BQ + warp) * DIM + lane * 4;
    #pragma unroll
    for (int j = 0; j < 4; j++) {
        g_qf[base1 + j]  = tv[j];
        g_qa8[base1 + j] = q8(tv[j], QA1);
    }
    if (lane == 0) g_zq[warp] = sq;

    // pad aux group-max entries with -inf (groups NGRP..NGRPP-1)
    if (lane < NGRPP - NGRP) {
        __half NI = __ushort_as_half((unsigned short)0xFC00);
        g_gmax[((size_t)0 * BQ + warp) * NGRPP + NGRP + lane] = NI;
        g_gmax[((size_t)1 * BQ + warp) * NGRPP + NGRP + lane] = NI;
    }
}

__global__ void prep_books(const float* __restrict__ z_rot_book,
                           const float* __restrict__ z_trans_book) {
    int warp = (blockIdx.x * blockDim.x + threadIdx.x) >> 5;
    int lane = threadIdx.x & 31;
    if (warp >= NBP) return;

    size_t base0 = (size_t)warp * DIM + lane * 4;
    size_t base1 = (size_t)NBP * DIM + base0;
    if (warp < NB) {
        float4 r = reinterpret_cast<const float4*>(z_rot_book + (size_t)warp * DIM)[lane];
        g_ba8[base0 + 0] = q8(r.x, 127.0f);
        g_ba8[base0 + 1] = q8(r.y, 127.0f);
        g_ba8[base0 + 2] = q8(r.z, 127.0f);
        g_ba8[base0 + 3] = q8(r.w, 127.0f);

        float4 t = reinterpret_cast<const float4*>(z_trans_book + (size_t)warp * DIM)[lane];
        float sq = t.x * t.x + t.y * t.y + t.z * t.z + t.w * t.w;
        #pragma unroll
        for (int o = 16; o; o >>= 1) sq += __shfl_xor_sync(0xFFFFFFFFu, sq, o);
        g_ba8[base1 + 0] = q8(t.x, QB1);
        g_ba8[base1 + 1] = q8(t.y, QB1);
        g_ba8[base1 + 2] = q8(t.z, QB1);
        g_ba8[base1 + 3] = q8(t.w, QB1);
        if (lane == 0) g_bq[warp] = sq;
    } else {
        #pragma unroll
        for (int j = 0; j < 4; j++) { g_ba8[base0 + j] = 0; g_ba8[base1 + j] = 0; }
        if (lane == 0) g_bq[warp] = 0.0f;
    }
}

// ======================= int8 IMMA GEMM ====================================
// Tiles: 128 rows x 128 int8 = 16 KB each (A, B), xor-swizzled 16B chunks.
#define SMEM_GEMM (2 * 16384 + 1024)

__global__ void __launch_bounds__(512, 2)
score_imma() {
    extern __shared__ char smem[];
    const int tid = threadIdx.x;
    const int p     = blockIdx.z;
    const int qbase = blockIdx.y * 128;
    const int nbase = blockIdx.x * 128;

    const signed char* srcs[2] = {
        g_qa8 + (size_t)(p * BQ + qbase) * DIM,
        g_ba8 + ((size_t)p * NBP + nbase) * DIM
    };
    #pragma unroll
    for (int b = 0; b < 2; b++) {
        char* dst = smem + b * 16384;
        const signed char* src = srcs[b];
        #pragma unroll
        for (int it = 0; it < 2; it++) {
            int idx = it * 512 + tid;     // 0..1023
            int row = idx >> 3;
            int c   = idx & 7;            // 16B chunk (8 per 128B row)
            uint4 v = *reinterpret_cast<const uint4*>(src + (size_t)row * DIM + c * 16);
            *reinterpret_cast<uint4*>(dst + row * 128 + ((c * 16) ^ ((row & 7) << 4))) = v;
        }
    }
    float* zqs = reinterpret_cast<float*>(smem + 32768);
    float* bqs = zqs + 128;
    if (tid < 128)       zqs[tid]       = (p == 1) ? g_zq[qbase + tid]       : 0.0f;
    else if (tid < 256)  bqs[tid - 128] = (p == 1) ? g_bq[nbase + tid - 128] : 0.0f;
    __syncthreads();

    const int lane = tid & 31;
    const int wid  = tid >> 5;
    const int wm = (wid >> 2) * 32;
    const int wn = (wid & 3) * 32;
    const int g  = lane >> 3;
    const int r8 = lane & 7;
    const uint32_t sx = (uint32_t)r8 << 4;
    const int aRowBase  = wm + r8 + ((g & 1) << 3);
    const int aChunkAdd = g >> 1;
    const int bRowBase  = wn + r8 + ((g >> 1) << 3);
    const int bChunkAdd = g & 1;

    uint32_t sb = smem_u32(smem);
    const uint32_t aB = sb;
    const uint32_t bB = sb + 16384u;

    int d[2][4][4];
    #pragma unroll
    for (int f = 0; f < 2; f++)
        #pragma unroll
        for (int j = 0; j < 4; j++)
            #pragma unroll
            for (int e = 0; e < 4; e++) d[f][j][e] = 0;

    #pragma unroll
    for (int s = 0; s < 4; s++) {        // 4 k32 steps
        uint32_t a[2][4], b[2][4];
        #pragma unroll
        for (int f = 0; f < 2; f++) {
            int row = aRowBase + f * 16;
            uint32_t ch = (uint32_t)(2 * s + aChunkAdd);
            ldsm_x4(aB + row * 128 + ((ch << 4) ^ sx), a[f]);
        }
        #pragma unroll
        for (int h = 0; h < 2; h++) {
            int row = bRowBase + h * 16;
            uint32_t ch = (uint32_t)(2 * s + bChunkAdd);
            ldsm_x4(bB + row * 128 + ((ch << 4) ^ sx), b[h]);
        }
        #pragma unroll
        for (int f = 0; f < 2; f++)
            #pragma unroll
            for (int j = 0; j < 4; j++)
                mma16832s8(d[f][j], a[f], &b[j >> 1][(j & 1) * 2]);
    }

    // ---- epilogue: dequant + fixups + fp16 store + per-32 group max
    const float invsc = (p == 0) ? INV0 : INV1;
    const bool tail = (nbase + 128) > NB;
    __half* S = reinterpret_cast<__half*>(g_s16v) + ((size_t)p * BQ + qbase) * NBP + nbase;
    #pragma unroll
    for (int f = 0; f < 2; f++) {
        int mA = wm + f * 16 + (lane >> 2);
        int mB = mA + 8;
        float zqA = zqs[mA], zqB = zqs[mB];
        __half2 mxA = __floats2half2_rn(-65504.0f, -65504.0f);
        __half2 mxB = mxA;
        #pragma unroll
        for (int j = 0; j < 4; j++) {
            int nl = wn + j * 8 + (lane & 3) * 2;
            float b0 = bqs[nl], b1 = bqs[nl + 1];
            float s0 = (float)d[f][j][0] * invsc - zqA - b0;
            float s1 = (float)d[f][j][1] * invsc - zqA - b1;
            float s2 = (float)d[f][j][2] * invsc - zqB - b0;
            float s3 = (float)d[f][j][3] * invsc - zqB - b1;
            if (tail) {
                int ng = nbase + nl;
                if (ng     >= NB) { s0 = -65504.0f; s2 = -65504.0f; }
                if (ng + 1 >= NB) { s1 = -65504.0f; s3 = -65504.0f; }
            }
            __half2 h0 = __floats2half2_rn(s0, s1);
            __half2 h1 = __floats2half2_rn(s2, s3);
            mxA = __hmax2(mxA, h0);
            mxB = __hmax2(mxB, h1);
            *reinterpret_cast<__half2*>(S + (size_t)mA * NBP + nl) = h0;
            *reinterpret_cast<__half2*>(S + (size_t)mB * NBP + nl) = h1;
        }
        __half2 mm = __halves2half2(__hmax(__low2half(mxA), __high2half(mxA)),
                                    __hmax(__low2half(mxB), __high2half(mxB)));
        unsigned int mu = *reinterpret_cast<unsigned int*>(&mm);
        __half2 ot;
        unsigned int ou;
        ou = __shfl_xor_sync(0xFFFFFFFFu, mu, 1);
        ot = *reinterpret_cast<__half2*>(&ou); mm = __hmax2(mm, ot);
        mu = *reinterpret_cast<unsigned int*>(&mm);
        ou = __shfl_xor_sync(0xFFFFFFFFu, mu, 2);
        ot = *reinterpret_cast<__half2*>(&ou); mm = __hmax2(mm, ot);
        if ((lane & 3) == 0) {
            int gc = (nbase + wn) >> 5;
            g_gmax[((size_t)p * BQ + qbase + mA) * NGRPP + gc] = __low2half(mm);
            g_gmax[((size_t)p * BQ + qbase + mB) * NGRPP + gc] = __high2half(mm);
        }
    }
}

// ============ fused candidate selection (top-64) + exact refine ============
__global__ void __launch_bounds__(256)
cand_refine_kernel(const float* __restrict__ z_rot_book,
                   const float* __restrict__ z_trans_book,
                   const float* __restrict__ rot_book,
                   const float* __restrict__ trans_book,
                   float* __restrict__ out) {
    const int p   = blockIdx.x >> 11;
    const int r   = blockIdx.x & 2047;
    const int tid = threadIdx.x;
    const int lane = tid & 31;
    const int wid  = tid >> 5;
    const __half* aux = g_gmax + ((size_t)p * BQ + r) * NGRPP;
    const uint4* row4 = g_s16v + (size_t)((size_t)p * BQ + r) * (NBP / 8);

    __shared__ __align__(16) unsigned int sbuf[2048];
    __shared__ unsigned int gsel[NCAND];
    __shared__ int scand[NCAND];
    __shared__ float sval[NCAND];
    __shared__ int   sidx[NCAND];
    __shared__ unsigned int sT0, sTE;
    __shared__ int scnt, scnt2;

    const uint4* sb4 = reinterpret_cast<const uint4*>(sbuf);

    // ---- Phase A1: up to 7 group keys per thread; T0 = 64th thread-max
    unsigned int gkey[7];
    unsigned int mybest = 0;
    #pragma unroll
    for (int k = 0; k < 7; k++) {
        int g = tid + (k << 8);
        unsigned int key = 0;
        if (g < NGRPP) {
            unsigned int hb = (unsigned int)__half_as_ushort(aux[g]);
            key = (h2ord(hb) << 16) | (0xFFFFu - (unsigned int)g);
        }
        gkey[k] = key;
        mybest = max(mybest, key);
    }
    sbuf[tid] = mybest;
    if (tid == 0) { scnt = 0; scnt2 = 0; }
    __syncthreads();
    {
        int rank = 0;
        #pragma unroll 8
        for (int i = 0; i < 64; i++) {
            uint4 v = sb4[i];
            rank += (v.x > mybest) + (v.y > mybest) + (v.z > mybest) + (v.w > mybest);
        }
        if (rank == NCAND - 1) sT0 = mybest;
    }
    __syncthreads();
    const unsigned int T0 = sT0;

    // ---- Phase A2: survivors >= T0 (<= 448), counting-rank -> top-64 groups
    sbuf[tid] = 0; sbuf[tid + 256] = 0;
    __syncthreads();
    #pragma unroll
    for (int k = 0; k < 7; k++)
        if (gkey[k] >= T0) sbuf[atomicAdd(&scnt, 1)] = gkey[k];
    __syncthreads();
    const int m = scnt;                  // 64 <= m <= 448
    {
        int mi4 = (m + 3) >> 2;
        #pragma unroll
        for (int sl = 0; sl < 2; sl++) {
            int slot = tid + sl * 256;
            if (slot < m) {
                unsigned int mk = sbuf[slot];
                int rk = 0;
                #pragma unroll 4
                for (int i = 0; i < mi4; i++) {
                    uint4 v = sb4[i];
                    rk += (v.x > mk) + (v.y > mk) + (v.z > mk) + (v.w > mk);
                }
                if (rk < NCAND) gsel[rk] = mk;
                if (rk == NCAND - 1) sTE = mk & 0xFFFF0000u;
            }
        }
    }
    __syncthreads();

    // ---- Phase B: gather 64 groups x 32 scores (threshold TE), counting-rank
    const unsigned int TE = sTE;
    #pragma unroll
    for (int z = 0; z < 8; z++) sbuf[tid + z * 256] = 0;
    __syncthreads();
    {
        int g   = (int)(0xFFFFu - (gsel[tid >> 2] & 0xFFFFu));
        int sub = tid & 3;
        uint4 v = row4[g * 4 + sub];
        unsigned int w[4] = {v.x, v.y, v.z, v.w};
        int nb = g * 32 + sub * 8;
        #pragma unroll
        for (int e = 0; e < 4; e++) {
            unsigned int lo = w[e] & 0xFFFFu;
            unsigned int hi = w[e] >> 16;
            unsigned int k0 = (h2ord(lo) << 16) | (0xFFFFu - (unsigned int)(nb + 2 * e));
            unsigned int k1 = (h2ord(hi) << 16) | (0xFFFFu - (unsigned int)(nb + 2 * e + 1));
            if (k0 >= TE) sbuf[atomicAdd(&scnt2, 1)] = k0;
            if (k1 >= TE) sbuf[atomicAdd(&scnt2, 1)] = k1;
        }
    }
    __syncthreads();
    const int m2 = scnt2;                // 64 <= m2 <= 2048
    {
        int mi4 = (m2 + 3) >> 2;
        for (int s = tid; s < m2; s += 256) {
            unsigned int kk = sbuf[s];
            int rk = 0;
            #pragma unroll 4
            for (int i = 0; i < mi4; i++) {
                uint4 v = sb4[i];
                rk += (v.x > kk) + (v.y > kk) + (v.z > kk) + (v.w > kk);
            }
            if (rk < NCAND) scand[rk] = (int)(0xFFFFu - (kk & 0xFFFFu));
        }
    }
    __syncthreads();

    // ---- exact refine: 64 fp32 dots (8 per warp)
    float4 a = reinterpret_cast<const float4*>(g_qf + (size_t)(p * BQ + r) * DIM)[lane];
    const float zq = (p == 1) ? g_zq[r] : 0.0f;
    const float* Bsrc = (p == 0) ? z_rot_book : z_trans_book;

    #pragma unroll
    for (int t = 0; t < NCAND / 8; t++) {
        int slot = wid * (NCAND / 8) + t;
        int ci = scand[slot];
        float4 b = reinterpret_cast<const float4*>(Bsrc + (size_t)ci * DIM)[lane];
        float sdot = a.x * b.x + a.y * b.y + a.z * b.z + a.w * b.w;
        #pragma unroll
        for (int o = 16; o; o >>= 1) sdot += __shfl_xor_sync(0xFFFFFFFFu, sdot, o);
        if (lane == 0) {
            sval[slot] = sdot - zq - ((p == 1) ? g_bq[ci] : 0.0f);
            sidx[slot] = ci;
        }
    }
    __syncthreads();

    // ---- final top-20 of 64 (warp 0, two slots per lane)
    if (wid == 0) {
        float v0 = sval[lane],      v1 = sval[lane + 32];
        int   i0 = sidx[lane],      i1 = sidx[lane + 32];
        const size_t BK = (size_t)BQ * TOPK;

        #pragma unroll
        for (int k = 0; k < TOPK; k++) {
            float bv; int bi; int bs;
            if (v0 > v1 || (v0 == v1 && i0 < i1)) { bv = v0; bi = i0; bs = 0; }
            else                                  { bv = v1; bi = i1; bs = 1; }
            int bl = lane;
            #pragma unroll
            for (int o = 16; o; o >>= 1) {
                float ov = __shfl_xor_sync(0xFFFFFFFFu, bv, o);
                int   oi = __shfl_xor_sync(0xFFFFFFFFu, bi, o);
                int   ol = __shfl_xor_sync(0xFFFFFFFFu, bl, o);
                int   os = __shfl_xor_sync(0xFFFFFFFFu, bs, o);
                if (ov > bv || (ov == bv && oi < bi)) { bv = ov; bi = oi; bl = ol; bs = os; }
            }
            if (lane == bl) {
                if (bs == 0) { v0 = -FLT_MAX; i0 = 0x7FFFFFFF; }
                else         { v1 = -FLT_MAX; i1 = 0x7FFFFFFF; }
            }
            if (lane == 0) {
                size_t rk = (size_t)r * TOPK + k;
                if (p == 0) {
                    out[rk]          = bv;
                    out[BK + rk]     = (float)bi;
                    out[2 * BK + rk] = rot_book[bi];
                } else {
                    out[3 * BK + rk] = bv;
                    out[4 * BK + rk] = (float)bi;
                    out[5 * BK + rk * 3 + 0] = trans_book[(size_t)bi * 3 + 0];
                    out[5 * BK + rk * 3 + 1] = trans_book[(size_t)bi * 3 + 1];
                    out[5 * BK + rk * 3 + 2] = trans_book[(size_t)bi * 3 + 2];
                }
            }
        }
    }
}

// ======================= launch ============================================
extern "C" void kernel_launch(void* const* d_in, const int* in_sizes, int n_in,
                              void* d_out, int out_size) {
    const float* z_rot        = (const float*)d_in[0];
    const float* z_trans      = (const float*)d_in[1];
    const float* z_rot_book   = (const float*)d_in[2];
    const float* z_trans_book = (const float*)d_in[3];
    const float* rot_book     = (const float*)d_in[4];
    const float* trans_book   = (const float*)d_in[5];
    float* out = (float*)d_out;

    prep_queries<<<BQ / 8, 256>>>(z_rot, z_trans);
    prep_books<<<(NBP + 7) / 8, 256>>>(z_rot_book, z_trans_book);

    cudaFuncSetAttribute(score_imma, cudaFuncAttributeMaxDynamicSharedMemorySize, SMEM_GEMM);
    dim3 grid(NBP / 128, BQ / 128, 2);
    score_imma<<<grid, 512, SMEM_GEMM>>>();

    cand_refine_kernel<<<2 * BQ, 256>>>(z_rot_book, z_trans_book, rot_book, trans_book, out);
}

// round 16
// speedup vs baseline: 1.1054x; 1.1054x over previous
#include <cuda_runtime.h>
#include <cuda_fp16.h>
#include <cfloat>
#include <cstdint>

// Problem constants
#define BQ    2048
#define NB    50000
#define NBP   50048     // 391*128
#define DIM   128
#define TOPK  20
#define NCAND 32
#define NGRP  1564      // NBP / 32
#define NGRPP 1568      // padded to 8*196

// ======================= device scratch ====================================
__device__ float  g_zq[BQ];
__device__ float  g_bq[NBP];
__device__ float  g_qf[2 * BQ * DIM];
__device__ __half g_qh16[2 * BQ * DIM];
__device__ __half g_bh16[(size_t)2 * NBP * DIM];
__device__ uint4  g_s16v[(size_t)2 * BQ * NBP / 8];   // approx scores fp16
__device__ __half g_gmax[(size_t)2 * BQ * NGRPP];     // per-32 group maxes

// ======================= helpers ===========================================
__device__ __forceinline__ uint32_t smem_u32(const void* p) {
    uint32_t a;
    asm("{ .reg .u64 t; cvta.to.shared.u64 t, %1; cvt.u32.u64 %0, t; }" : "=r"(a) : "l"(p));
    return a;
}
__device__ __forceinline__ void ldsm_x4(uint32_t addr, uint32_t* r) {
    asm volatile("ldmatrix.sync.aligned.m8n8.x4.shared.b16 {%0,%1,%2,%3}, [%4];"
        : "=r"(r[0]), "=r"(r[1]), "=r"(r[2]), "=r"(r[3]) : "r"(addr));
}
// fp16-accumulate MMA
__device__ __forceinline__ void mma16816h(uint32_t* d, const uint32_t* a, const uint32_t* b) {
    asm volatile("mma.sync.aligned.m16n8k16.row.col.f16.f16.f16.f16 "
        "{%0,%1}, {%2,%3,%4,%5}, {%6,%7}, {%0,%1};"
        : "+r"(d[0]), "+r"(d[1])
        : "r"(a[0]), "r"(a[1]), "r"(a[2]), "r"(a[3]), "r"(b[0]), "r"(b[1]));
}
// order-preserving transform: half bits (16) -> uint16 with integer order
__device__ __forceinline__ unsigned int h2ord(unsigned int u) {
    return u ^ (0x8000u | (0x7FFFu & (0u - (u >> 15))));
}

// ======================= prep kernels ======================================
__global__ void prep_queries(const float* __restrict__ z_rot,
                             const float* __restrict__ z_trans) {
    int warp = (blockIdx.x * blockDim.x + threadIdx.x) >> 5;
    int lane = threadIdx.x & 31;
    if (warp >= BQ) return;

    float4 v = reinterpret_cast<const float4*>(z_rot + (size_t)warp * DIM)[lane];
    float s = v.x * v.x + v.y * v.y + v.z * v.z + v.w * v.w;
    #pragma unroll
    for (int o = 16; o; o >>= 1) s += __shfl_xor_sync(0xFFFFFFFFu, s, o);
    float inv = 1.0f / sqrtf(s);
    float rv[4] = {v.x * inv, v.y * inv, v.z * inv, v.w * inv};
    size_t base0 = (size_t)warp * DIM + lane * 4;
    #pragma unroll
    for (int j = 0; j < 4; j++) {
        g_qf[base0 + j]   = rv[j];
        g_qh16[base0 + j] = __float2half_rn(rv[j]);
    }

    float4 t = reinterpret_cast<const float4*>(z_trans + (size_t)warp * DIM)[lane];
    float sq = t.x * t.x + t.y * t.y + t.z * t.z + t.w * t.w;
    #pragma unroll
    for (int o = 16; o; o >>= 1) sq += __shfl_xor_sync(0xFFFFFFFFu, sq, o);
    float tv[4] = {2.0f * t.x, 2.0f * t.y, 2.0f * t.z, 2.0f * t.w};
    size_t base1 = (size_t)(BQ + warp) * DIM + lane * 4;
    #pragma unroll
    for (int j = 0; j < 4; j++) {
        g_qf[base1 + j]   = tv[j];
        g_qh16[base1 + j] = __float2half_rn(tv[j]);
    }
    if (lane == 0) g_zq[warp] = sq;

    // pad aux group-max entries with -inf (groups NGRP..NGRPP-1)
    if (lane < NGRPP - NGRP) {
        __half NI = __ushort_as_half((unsigned short)0xFC00);
        g_gmax[((size_t)0 * BQ + warp) * NGRPP + NGRP + lane] = NI;
        g_gmax[((size_t)1 * BQ + warp) * NGRPP + NGRP + lane] = NI;
    }
}

__global__ void prep_books(const float* __restrict__ z_rot_book,
                           const float* __restrict__ z_trans_book) {
    int warp = (blockIdx.x * blockDim.x + threadIdx.x) >> 5;
    int lane = threadIdx.x & 31;
    if (warp >= NBP) return;

    size_t base0 = (size_t)warp * DIM + lane * 4;
    size_t base1 = (size_t)NBP * DIM + base0;
    if (warp < NB) {
        float4 r = reinterpret_cast<const float4*>(z_rot_book + (size_t)warp * DIM)[lane];
        g_bh16[base0 + 0] = __float2half_rn(r.x);
        g_bh16[base0 + 1] = __float2half_rn(r.y);
        g_bh16[base0 + 2] = __float2half_rn(r.z);
        g_bh16[base0 + 3] = __float2half_rn(r.w);

        float4 t = reinterpret_cast<const float4*>(z_trans_book + (size_t)warp * DIM)[lane];
        float sq = t.x * t.x + t.y * t.y + t.z * t.z + t.w * t.w;
        #pragma unroll
        for (int o = 16; o; o >>= 1) sq += __shfl_xor_sync(0xFFFFFFFFu, sq, o);
        g_bh16[base1 + 0] = __float2half_rn(t.x);
        g_bh16[base1 + 1] = __float2half_rn(t.y);
        g_bh16[base1 + 2] = __float2half_rn(t.z);
        g_bh16[base1 + 3] = __float2half_rn(t.w);
        if (lane == 0) g_bq[warp] = sq;
    } else {
        __half z = __float2half_rn(0.0f);
        #pragma unroll
        for (int j = 0; j < 4; j++) { g_bh16[base0 + j] = z; g_bh16[base1 + j] = z; }
        if (lane == 0) g_bq[warp] = 0.0f;
    }
}

// ======================= single-pass fp16 HMMA GEMM (f16 accum) ============
#define SMEM_GEMM (2 * 32768 + 1024)

__global__ void __launch_bounds__(512, 2)
score_hmma1(int p) {
    extern __shared__ char smem[];
    const int tid = threadIdx.x;
    const int qbase = blockIdx.y * 128;
    const int nbase = blockIdx.x * 128;

    const __half* srcs[2] = {
        g_qh16 + (size_t)(p * BQ + qbase) * DIM,
        g_bh16 + ((size_t)p * NBP + nbase) * DIM
    };
    #pragma unroll
    for (int b = 0; b < 2; b++) {
        char* dst = smem + b * 32768;
        const __half* src = srcs[b];
        #pragma unroll
        for (int it = 0; it < 4; it++) {
            int idx = it * 512 + tid;
            int row = idx >> 4;
            int c   = idx & 15;
            uint4 v = *reinterpret_cast<const uint4*>(src + (size_t)row * DIM + c * 8);
            *reinterpret_cast<uint4*>(dst + row * 256 + ((c * 16) ^ ((row & 7) << 4))) = v;
        }
    }
    float* zqs = reinterpret_cast<float*>(smem + 65536);
    float* bqs = zqs + 128;
    if (tid < 128)       zqs[tid]       = (p == 1) ? g_zq[qbase + tid]       : 0.0f;
    else if (tid < 256)  bqs[tid - 128] = (p == 1) ? g_bq[nbase + tid - 128] : 0.0f;
    __syncthreads();

    const int lane = tid & 31;
    const int wid  = tid >> 5;
    const int wm = (wid >> 2) * 32;
    const int wn = (wid & 3) * 32;
    const int g  = lane >> 3;
    const int r8 = lane & 7;
    const uint32_t sx = (uint32_t)r8 << 4;
    const int aRowBase  = wm + r8 + ((g & 1) << 3);
    const int aChunkAdd = g >> 1;
    const int bRowBase  = wn + r8 + ((g >> 1) << 3);
    const int bChunkAdd = g & 1;

    uint32_t sb = smem_u32(smem);
    const uint32_t aB = sb;
    const uint32_t bB = sb + 32768u;

    uint32_t dh[2][4][2];
    #pragma unroll
    for (int f = 0; f < 2; f++)
        #pragma unroll
        for (int j = 0; j < 4; j++) { dh[f][j][0] = 0u; dh[f][j][1] = 0u; }

    #pragma unroll
    for (int s = 0; s < 8; s++) {
        uint32_t a[2][4], b[2][4];
        #pragma unroll
        for (int f = 0; f < 2; f++) {
            int row = aRowBase + f * 16;
            uint32_t ch = (uint32_t)(2 * s + aChunkAdd);
            ldsm_x4(aB + row * 256 + ((ch << 4) ^ sx), a[f]);
        }
        #pragma unroll
        for (int h = 0; h < 2; h++) {
            int row = bRowBase + h * 16;
            uint32_t ch = (uint32_t)(2 * s + bChunkAdd);
            ldsm_x4(bB + row * 256 + ((ch << 4) ^ sx), b[h]);
        }
        #pragma unroll
        for (int f = 0; f < 2; f++)
            #pragma unroll
            for (int j = 0; j < 4; j++)
                mma16816h(dh[f][j], a[f], &b[j >> 1][(j & 1) * 2]);
    }

    // ---- epilogue: fp32 fixups + fp16 store + per-32 group max
    const bool tail = (nbase + 128) > NB;
    __half* S = reinterpret_cast<__half*>(g_s16v) + ((size_t)p * BQ + qbase) * NBP + nbase;
    #pragma unroll
    for (int f = 0; f < 2; f++) {
        int mA = wm + f * 16 + (lane >> 2);
        int mB = mA + 8;
        float zqA = zqs[mA], zqB = zqs[mB];
        __half2 mxA = __floats2half2_rn(-65504.0f, -65504.0f);
        __half2 mxB = mxA;
        #pragma unroll
        for (int j = 0; j < 4; j++) {
            int nl = wn + j * 8 + (lane & 3) * 2;
            float b0 = bqs[nl], b1 = bqs[nl + 1];
            float2 f01 = __half22float2(*reinterpret_cast<__half2*>(&dh[f][j][0]));
            float2 f23 = __half22float2(*reinterpret_cast<__half2*>(&dh[f][j][1]));
            float s0 = f01.x - zqA - b0;
            float s1 = f01.y - zqA - b1;
            float s2 = f23.x - zqB - b0;
            float s3 = f23.y - zqB - b1;
            if (tail) {
                int ng = nbase + nl;
                if (ng     >= NB) { s0 = -65504.0f; s2 = -65504.0f; }
                if (ng + 1 >= NB) { s1 = -65504.0f; s3 = -65504.0f; }
            }
            __half2 h0 = __floats2half2_rn(s0, s1);
            __half2 h1 = __floats2half2_rn(s2, s3);
            mxA = __hmax2(mxA, h0);
            mxB = __hmax2(mxB, h1);
            *reinterpret_cast<__half2*>(S + (size_t)mA * NBP + nl) = h0;
            *reinterpret_cast<__half2*>(S + (size_t)mB * NBP + nl) = h1;
        }
        __half2 mm = __halves2half2(__hmax(__low2half(mxA), __high2half(mxA)),
                                    __hmax(__low2half(mxB), __high2half(mxB)));
        unsigned int mu = *reinterpret_cast<unsigned int*>(&mm);
        __half2 ot;
        unsigned int ou;
        ou = __shfl_xor_sync(0xFFFFFFFFu, mu, 1);
        ot = *reinterpret_cast<__half2*>(&ou); mm = __hmax2(mm, ot);
        mu = *reinterpret_cast<unsigned int*>(&mm);
        ou = __shfl_xor_sync(0xFFFFFFFFu, mu, 2);
        ot = *reinterpret_cast<__half2*>(&ou); mm = __hmax2(mm, ot);
        if ((lane & 3) == 0) {
            int gc = (nbase + wn) >> 5;
            g_gmax[((size_t)p * BQ + qbase + mA) * NGRPP + gc] = __low2half(mm);
            g_gmax[((size_t)p * BQ + qbase + mB) * NGRPP + gc] = __high2half(mm);
        }
    }
}

// ============ fused candidate selection + exact refine + output ============
__global__ void __launch_bounds__(256)
cand_refine_kernel(int p,
                   const float* __restrict__ z_rot_book,
                   const float* __restrict__ z_trans_book,
                   const float* __restrict__ rot_book,
                   const float* __restrict__ trans_book,
                   float* __restrict__ out) {
    const int r   = blockIdx.x;
    const int tid = threadIdx.x;
    const int lane = tid & 31;
    const int wid  = tid >> 5;
    const __half* aux = g_gmax + ((size_t)p * BQ + r) * NGRPP;
    const uint4* row4 = g_s16v + (size_t)((size_t)p * BQ + r) * (NBP / 8);

    __shared__ __align__(16) unsigned int sbuf[1024];
    __shared__ unsigned int gsel[32];
    __shared__ int scand[NCAND];
    __shared__ float sval[NCAND];
    __shared__ int   sidx[NCAND];
    __shared__ unsigned int sT0, sTE;
    __shared__ int scnt, scnt2;

    const uint4* sb4 = reinterpret_cast<const uint4*>(sbuf);

    // ---- Phase A1: up to 7 group keys per thread (stride-256, coalesced)
    unsigned int gkey[7];
    unsigned int mybest = 0;
    #pragma unroll
    for (int k = 0; k < 7; k++) {
        int g = tid + (k << 8);
        unsigned int key = 0;
        if (g < NGRPP) {
            unsigned int hb = (unsigned int)__half_as_ushort(aux[g]);
            key = (h2ord(hb) << 16) | (0xFFFFu - (unsigned int)g);
        }
        gkey[k] = key;
        mybest = max(mybest, key);
    }

    sbuf[tid] = mybest;
    if (tid == 0) scnt = 0;
    __syncthreads();

    // exact rank of my thread-max among 256 (uint4 broadcast reads)
    {
        int rank = 0;
        #pragma unroll 8
        for (int i = 0; i < 64; i++) {
            uint4 v = sb4[i];
            rank += (v.x > mybest) + (v.y > mybest) + (v.z > mybest) + (v.w > mybest);
        }
        if (rank == 31) sT0 = mybest;
    }
    __syncthreads();
    const unsigned int T0 = sT0;

    // ---- Phase A2: survivors >= T0 (<= 224), counting-rank
    sbuf[tid] = 0;
    __syncthreads();
    #pragma unroll
    for (int k = 0; k < 7; k++)
        if (gkey[k] >= T0) sbuf[atomicAdd(&scnt, 1)] = gkey[k];
    __syncthreads();
    const int m = scnt;
    {
        unsigned int mk = sbuf[tid];
        int rk = 0;
        int mi4 = (m + 3) >> 2;
        #pragma unroll 4
        for (int i = 0; i < mi4; i++) {
            uint4 v = sb4[i];
            rk += (v.x > mk) + (v.y > mk) + (v.z > mk) + (v.w > mk);
        }
        if (tid < m) {
            if (rk < 32) gsel[rk] = mk;
            if (rk == 31) sTE = mk & 0xFFFF0000u;
        }
    }
    if (tid == 0) scnt2 = 0;
    __syncthreads();

    // ---- Phase B: gather 32 groups x 32 scores with fused threshold
    const unsigned int TE = sTE;
    sbuf[tid] = 0; sbuf[tid + 256] = 0; sbuf[tid + 512] = 0; sbuf[tid + 768] = 0;
    __syncthreads();
    if (tid < 128) {
        int g   = (int)(0xFFFFu - (gsel[tid >> 2] & 0xFFFFu));
        int sub = tid & 3;
        uint4 v = row4[g * 4 + sub];
        unsigned int w[4] = {v.x, v.y, v.z, v.w};
        int nb = g * 32 + sub * 8;
        #pragma unroll
        for (int e = 0; e < 4; e++) {
            unsigned int lo = w[e] & 0xFFFFu;
            unsigned int hi = w[e] >> 16;
            unsigned int k0 = (h2ord(lo) << 16) | (0xFFFFu - (unsigned int)(nb + 2 * e));
            unsigned int k1 = (h2ord(hi) << 16) | (0xFFFFu - (unsigned int)(nb + 2 * e + 1));
            if (k0 >= TE) sbuf[atomicAdd(&scnt2, 1)] = k0;
            if (k1 >= TE) sbuf[atomicAdd(&scnt2, 1)] = k1;
        }
    }
    __syncthreads();
    const int m2 = scnt2;
    {
        int mi4 = (m2 + 3) >> 2;
        for (int s = tid; s < m2; s += 256) {
            unsigned int kk = sbuf[s];
            int rk = 0;
            #pragma unroll 4
            for (int i = 0; i < mi4; i++) {
                uint4 v = sb4[i];
                rk += (v.x > kk) + (v.y > kk) + (v.z > kk) + (v.w > kk);
            }
            if (rk < 32) scand[rk] = (int)(0xFFFFu - (kk & 0xFFFFu));
        }
    }
    __syncthreads();

    // ---- exact refine: 32 fp32 dots over the candidates
    float4 a = reinterpret_cast<const float4*>(g_qf + (size_t)(p * BQ + r) * DIM)[lane];
    const float zq = (p == 1) ? g_zq[r] : 0.0f;
    const float* Bsrc = (p == 0) ? z_rot_book : z_trans_book;

    #pragma unroll
    for (int t = 0; t < NCAND / 8; t++) {
        int slot = wid * (NCAND / 8) + t;
        int ci = scand[slot];
        float4 b = reinterpret_cast<const float4*>(Bsrc + (size_t)ci * DIM)[lane];
        float sdot = a.x * b.x + a.y * b.y + a.z * b.z + a.w * b.w;
        #pragma unroll
        for (int o = 16; o; o >>= 1) sdot += __shfl_xor_sync(0xFFFFFFFFu, sdot, o);
        if (lane == 0) {
            sval[slot] = sdot - zq - ((p == 1) ? g_bq[ci] : 0.0f);
            sidx[slot] = ci;
        }
    }
    __syncthreads();

    if (wid == 0) {
        float v = sval[lane];
        int  ix = sidx[lane];
        const size_t BK = (size_t)BQ * TOPK;

        #pragma unroll
        for (int k = 0; k < TOPK; k++) {
            float bv = v; int bi = ix; int bl = lane;
            #pragma unroll
            for (int o = 16; o; o >>= 1) {
                float ov = __shfl_xor_sync(0xFFFFFFFFu, bv, o);
                int   oi = __shfl_xor_sync(0xFFFFFFFFu, bi, o);
                int   ol = __shfl_xor_sync(0xFFFFFFFFu, bl, o);
                if (ov > bv || (ov == bv && oi < bi)) { bv = ov; bi = oi; bl = ol; }
            }
            if (lane == bl) { v = -FLT_MAX; ix = 0x7FFFFFFF; }
            if (lane == 0) {
                size_t rk = (size_t)r * TOPK + k;
                if (p == 0) {
                    out[rk]          = bv;
                    out[BK + rk]     = (float)bi;
                    out[2 * BK + rk] = rot_book[bi];
                } else {
                    out[3 * BK + rk] = bv;
                    out[4 * BK + rk] = (float)bi;
                    out[5 * BK + rk * 3 + 0] = trans_book[(size_t)bi * 3 + 0];
                    out[5 * BK + rk * 3 + 1] = trans_book[(size_t)bi * 3 + 1];
                    out[5 * BK + rk * 3 + 2] = trans_book[(size_t)bi * 3 + 2];
                }
            }
        }
    }
}

// ======================= launch ============================================
extern "C" void kernel_launch(void* const* d_in, const int* in_sizes, int n_in,
                              void* d_out, int out_size) {
    const float* z_rot        = (const float*)d_in[0];
    const float* z_trans      = (const float*)d_in[1];
    const float* z_rot_book   = (const float*)d_in[2];
    const float* z_trans_book = (const float*)d_in[3];
    const float* rot_book     = (const float*)d_in[4];
    const float* trans_book   = (const float*)d_in[5];
    float* out = (float*)d_out;

    // side stream + events, created once (first call is the uncaptured
    // correctness run; capture call reuses them — work is identical each call)
    static cudaStream_t s2 = nullptr;
    static cudaEvent_t evFork = nullptr, evBooks = nullptr, evG0 = nullptr, evC0 = nullptr;
    static bool attr = false;
    if (!s2) {
        cudaStreamCreateWithFlags(&s2, cudaStreamNonBlocking);
        cudaEventCreateWithFlags(&evFork,  cudaEventDisableTiming);
        cudaEventCreateWithFlags(&evBooks, cudaEventDisableTiming);
        cudaEventCreateWithFlags(&evG0,    cudaEventDisableTiming);
        cudaEventCreateWithFlags(&evC0,    cudaEventDisableTiming);
    }
    if (!attr) {
        cudaFuncSetAttribute(score_hmma1, cudaFuncAttributeMaxDynamicSharedMemorySize, SMEM_GEMM);
        attr = true;
    }

    // fork side stream from main
    cudaEventRecord(evFork, 0);
    cudaStreamWaitEvent(s2, evFork, 0);

    // prep: books on side stream, queries on main (concurrent)
    prep_books<<<(NBP + 7) / 8, 256, 0, s2>>>(z_rot_book, z_trans_book);
    cudaEventRecord(evBooks, s2);
    prep_queries<<<BQ / 8, 256>>>(z_rot, z_trans);
    cudaStreamWaitEvent(0, evBooks, 0);

    // GEMM p=0 on main
    dim3 ggrid(NBP / 128, BQ / 128);
    score_hmma1<<<ggrid, 512, SMEM_GEMM>>>(0);
    cudaEventRecord(evG0, 0);

    // GEMM p=1 on main, cand_refine p=0 on side stream (overlapped)
    score_hmma1<<<ggrid, 512, SMEM_GEMM>>>(1);
    cudaStreamWaitEvent(s2, evG0, 0);
    cand_refine_kernel<<<BQ, 256, 0, s2>>>(0, z_rot_book, z_trans_book,
                                           rot_book, trans_book, out);
    cudaEventRecord(evC0, s2);

    // cand_refine p=1 on main, then join side stream
    cand_refine_kernel<<<BQ, 256>>>(1, z_rot_book, z_trans_book,
                                    rot_book, trans_book, out);
    cudaStreamWaitEvent(0, evC0, 0);
}

// round 17
// speedup vs baseline: 1.1969x; 1.0828x over previous
#include <cuda_runtime.h>
#include <cuda_fp16.h>
#include <cfloat>
#include <cstdint>

// Problem constants
#define BQ    2048
#define NB    50000
#define NBP   50048     // 391*128
#define DIM   128
#define TOPK  20
#define NCAND 32
#define NGRP  1564      // NBP / 32
#define NGRPP 1568      // padded to 8*196

// ======================= device scratch ====================================
__device__ float  g_zq[BQ];
__device__ float  g_bq[NBP];
__device__ float  g_qf[2 * BQ * DIM];
__device__ __half g_qh16[2 * BQ * DIM];
__device__ __half g_bh16[(size_t)2 * NBP * DIM];
__device__ uint4  g_s16v[(size_t)2 * BQ * NBP / 8];   // approx scores fp16
__device__ __half g_gmax[(size_t)2 * BQ * NGRPP];     // per-32 group maxes

// ======================= helpers ===========================================
__device__ __forceinline__ uint32_t smem_u32(const void* p) {
    uint32_t a;
    asm("{ .reg .u64 t; cvta.to.shared.u64 t, %1; cvt.u32.u64 %0, t; }" : "=r"(a) : "l"(p));
    return a;
}
__device__ __forceinline__ void ldsm_x4(uint32_t addr, uint32_t* r) {
    asm volatile("ldmatrix.sync.aligned.m8n8.x4.shared.b16 {%0,%1,%2,%3}, [%4];"
        : "=r"(r[0]), "=r"(r[1]), "=r"(r[2]), "=r"(r[3]) : "r"(addr));
}
// fp16-accumulate MMA
__device__ __forceinline__ void mma16816h(uint32_t* d, const uint32_t* a, const uint32_t* b) {
    asm volatile("mma.sync.aligned.m16n8k16.row.col.f16.f16.f16.f16 "
        "{%0,%1}, {%2,%3,%4,%5}, {%6,%7}, {%0,%1};"
        : "+r"(d[0]), "+r"(d[1])
        : "r"(a[0]), "r"(a[1]), "r"(a[2]), "r"(a[3]), "r"(b[0]), "r"(b[1]));
}
// order-preserving transform: half bits (16) -> uint16 with integer order
__device__ __forceinline__ unsigned int h2ord(unsigned int u) {
    return u ^ (0x8000u | (0x7FFFu & (0u - (u >> 15))));
}

// ======================= prep kernels ======================================
__global__ void prep_queries(const float* __restrict__ z_rot,
                             const float* __restrict__ z_trans) {
    int warp = (blockIdx.x * blockDim.x + threadIdx.x) >> 5;
    int lane = threadIdx.x & 31;
    if (warp >= BQ) return;

    float4 v = reinterpret_cast<const float4*>(z_rot + (size_t)warp * DIM)[lane];
    float s = v.x * v.x + v.y * v.y + v.z * v.z + v.w * v.w;
    #pragma unroll
    for (int o = 16; o; o >>= 1) s += __shfl_xor_sync(0xFFFFFFFFu, s, o);
    float inv = 1.0f / sqrtf(s);
    float rv[4] = {v.x * inv, v.y * inv, v.z * inv, v.w * inv};
    size_t base0 = (size_t)warp * DIM + lane * 4;
    #pragma unroll
    for (int j = 0; j < 4; j++) {
        g_qf[base0 + j]   = rv[j];
        g_qh16[base0 + j] = __float2half_rn(rv[j]);
    }

    float4 t = reinterpret_cast<const float4*>(z_trans + (size_t)warp * DIM)[lane];
    float sq = t.x * t.x + t.y * t.y + t.z * t.z + t.w * t.w;
    #pragma unroll
    for (int o = 16; o; o >>= 1) sq += __shfl_xor_sync(0xFFFFFFFFu, sq, o);
    float tv[4] = {2.0f * t.x, 2.0f * t.y, 2.0f * t.z, 2.0f * t.w};
    size_t base1 = (size_t)(BQ + warp) * DIM + lane * 4;
    #pragma unroll
    for (int j = 0; j < 4; j++) {
        g_qf[base1 + j]   = tv[j];
        g_qh16[base1 + j] = __float2half_rn(tv[j]);
    }
    if (lane == 0) g_zq[warp] = sq;

    // pad aux group-max entries with -inf (groups NGRP..NGRPP-1)
    if (lane < NGRPP - NGRP) {
        __half NI = __ushort_as_half((unsigned short)0xFC00);
        g_gmax[((size_t)0 * BQ + warp) * NGRPP + NGRP + lane] = NI;
        g_gmax[((size_t)1 * BQ + warp) * NGRPP + NGRP + lane] = NI;
    }
}

__global__ void prep_books(const float* __restrict__ z_rot_book,
                           const float* __restrict__ z_trans_book) {
    int warp = (blockIdx.x * blockDim.x + threadIdx.x) >> 5;
    int lane = threadIdx.x & 31;
    if (warp >= NBP) return;

    size_t base0 = (size_t)warp * DIM + lane * 4;
    size_t base1 = (size_t)NBP * DIM + base0;
    if (warp < NB) {
        float4 r = reinterpret_cast<const float4*>(z_rot_book + (size_t)warp * DIM)[lane];
        g_bh16[base0 + 0] = __float2half_rn(r.x);
        g_bh16[base0 + 1] = __float2half_rn(r.y);
        g_bh16[base0 + 2] = __float2half_rn(r.z);
        g_bh16[base0 + 3] = __float2half_rn(r.w);

        float4 t = reinterpret_cast<const float4*>(z_trans_book + (size_t)warp * DIM)[lane];
        float sq = t.x * t.x + t.y * t.y + t.z * t.z + t.w * t.w;
        #pragma unroll
        for (int o = 16; o; o >>= 1) sq += __shfl_xor_sync(0xFFFFFFFFu, sq, o);
        g_bh16[base1 + 0] = __float2half_rn(t.x);
        g_bh16[base1 + 1] = __float2half_rn(t.y);
        g_bh16[base1 + 2] = __float2half_rn(t.z);
        g_bh16[base1 + 3] = __float2half_rn(t.w);
        if (lane == 0) g_bq[warp] = sq;
    } else {
        __half z = __float2half_rn(0.0f);
        #pragma unroll
        for (int j = 0; j < 4; j++) { g_bh16[base0 + j] = z; g_bh16[base1 + j] = z; }
        if (lane == 0) g_bq[warp] = 0.0f;
    }
}

// ============== fp16 HMMA GEMM: 256q x 128n CTA, 64x64 warp tiles ==========
// 256 threads, 8 warps (4x2). A tile 256x128 (64KB), B tile 128x128 (32KB).
#define SM_A    0
#define SM_B    65536
#define SM_FIX  98304
#define SMEM_GEMM (98304 + 1024 + 512)

__global__ void __launch_bounds__(256, 2)
score_hmma1(int p) {
    extern __shared__ char smem[];
    const int tid = threadIdx.x;
    const int qbase = blockIdx.y * 256;
    const int nbase = blockIdx.x * 128;

    // ---- load A tile (256 rows x 128 halfs), swizzled
    {
        const __half* src = g_qh16 + (size_t)(p * BQ + qbase) * DIM;
        #pragma unroll
        for (int it = 0; it < 16; it++) {
            int idx = it * 256 + tid;
            int row = idx >> 4;
            int c   = idx & 15;
            uint4 v = *reinterpret_cast<const uint4*>(src + (size_t)row * DIM + c * 8);
            *reinterpret_cast<uint4*>(smem + SM_A + row * 256 + ((c * 16) ^ ((row & 7) << 4))) = v;
        }
    }
    // ---- load B tile (128 rows x 128 halfs), swizzled
    {
        const __half* src = g_bh16 + ((size_t)p * NBP + nbase) * DIM;
        #pragma unroll
        for (int it = 0; it < 8; it++) {
            int idx = it * 256 + tid;
            int row = idx >> 4;
            int c   = idx & 15;
            uint4 v = *reinterpret_cast<const uint4*>(src + (size_t)row * DIM + c * 8);
            *reinterpret_cast<uint4*>(smem + SM_B + row * 256 + ((c * 16) ^ ((row & 7) << 4))) = v;
        }
    }
    float* zqs = reinterpret_cast<float*>(smem + SM_FIX);
    float* bqs = zqs + 256;
    zqs[tid] = (p == 1) ? g_zq[qbase + tid] : 0.0f;
    if (tid < 128) bqs[tid] = (p == 1) ? g_bq[nbase + tid] : 0.0f;
    __syncthreads();

    const int lane = tid & 31;
    const int wid  = tid >> 5;
    const int wm = (wid >> 1) * 64;      // 0,64,128,192
    const int wn = (wid & 1) * 64;       // 0,64
    const int g  = lane >> 3;
    const int r8 = lane & 7;
    const uint32_t sx = (uint32_t)r8 << 4;
    const int aRowBase  = wm + r8 + ((g & 1) << 3);
    const int aChunkAdd = g >> 1;
    const int bRowBase  = wn + r8 + ((g >> 1) << 3);
    const int bChunkAdd = g & 1;

    uint32_t sb = smem_u32(smem);
    const uint32_t aB = sb + SM_A;
    const uint32_t bB = sb + SM_B;

    uint32_t dh[4][8][2];
    #pragma unroll
    for (int f = 0; f < 4; f++)
        #pragma unroll
        for (int j = 0; j < 8; j++) { dh[f][j][0] = 0u; dh[f][j][1] = 0u; }

    #pragma unroll
    for (int s = 0; s < 8; s++) {
        uint32_t a[4][4], b[4][4];
        #pragma unroll
        for (int f = 0; f < 4; f++) {
            int row = aRowBase + f * 16;
            uint32_t ch = (uint32_t)(2 * s + aChunkAdd);
            ldsm_x4(aB + row * 256 + ((ch << 4) ^ sx), a[f]);
        }
        #pragma unroll
        for (int h = 0; h < 4; h++) {
            int row = bRowBase + h * 16;
            uint32_t ch = (uint32_t)(2 * s + bChunkAdd);
            ldsm_x4(bB + row * 256 + ((ch << 4) ^ sx), b[h]);
        }
        #pragma unroll
        for (int f = 0; f < 4; f++)
            #pragma unroll
            for (int j = 0; j < 8; j++)
                mma16816h(dh[f][j], a[f], &b[j >> 1][(j & 1) * 2]);
    }

    // ---- epilogue: fp32 fixups + fp16 store + per-32 group max (2 groups)
    const bool tail = (nbase + 128) > NB;
    __half* S = reinterpret_cast<__half*>(g_s16v) + ((size_t)p * BQ + qbase) * NBP + nbase;
    #pragma unroll
    for (int f = 0; f < 4; f++) {
        int mA = wm + f * 16 + (lane >> 2);
        int mB = mA + 8;
        float zqA = zqs[mA], zqB = zqs[mB];
        #pragma unroll
        for (int g2 = 0; g2 < 2; g2++) {
            __half2 mxA = __floats2half2_rn(-65504.0f, -65504.0f);
            __half2 mxB = mxA;
            #pragma unroll
            for (int jj = 0; jj < 4; jj++) {
                int j  = g2 * 4 + jj;
                int nl = wn + j * 8 + (lane & 3) * 2;
                float b0 = bqs[nl], b1 = bqs[nl + 1];
                float2 f01 = __half22float2(*reinterpret_cast<__half2*>(&dh[f][j][0]));
                float2 f23 = __half22float2(*reinterpret_cast<__half2*>(&dh[f][j][1]));
                float s0 = f01.x - zqA - b0;
                float s1 = f01.y - zqA - b1;
                float s2 = f23.x - zqB - b0;
                float s3 = f23.y - zqB - b1;
                if (tail) {
                    int ng = nbase + nl;
                    if (ng     >= NB) { s0 = -65504.0f; s2 = -65504.0f; }
                    if (ng + 1 >= NB) { s1 = -65504.0f; s3 = -65504.0f; }
                }
                __half2 h0 = __floats2half2_rn(s0, s1);
                __half2 h1 = __floats2half2_rn(s2, s3);
                mxA = __hmax2(mxA, h0);
                mxB = __hmax2(mxB, h1);
                *reinterpret_cast<__half2*>(S + (size_t)mA * NBP + nl) = h0;
                *reinterpret_cast<__half2*>(S + (size_t)mB * NBP + nl) = h1;
            }
            __half2 mm = __halves2half2(__hmax(__low2half(mxA), __high2half(mxA)),
                                        __hmax(__low2half(mxB), __high2half(mxB)));
            unsigned int mu = *reinterpret_cast<unsigned int*>(&mm);
            __half2 ot;
            unsigned int ou;
            ou = __shfl_xor_sync(0xFFFFFFFFu, mu, 1);
            ot = *reinterpret_cast<__half2*>(&ou); mm = __hmax2(mm, ot);
            mu = *reinterpret_cast<unsigned int*>(&mm);
            ou = __shfl_xor_sync(0xFFFFFFFFu, mu, 2);
            ot = *reinterpret_cast<__half2*>(&ou); mm = __hmax2(mm, ot);
            if ((lane & 3) == 0) {
                int gc = (nbase + wn + g2 * 32) >> 5;
                g_gmax[((size_t)p * BQ + qbase + mA) * NGRPP + gc] = __low2half(mm);
                g_gmax[((size_t)p * BQ + qbase + mB) * NGRPP + gc] = __high2half(mm);
            }
        }
    }
}

// ============ fused candidate selection + exact refine + output ============
__global__ void __launch_bounds__(256)
cand_refine_kernel(int p,
                   const float* __restrict__ z_rot_book,
                   const float* __restrict__ z_trans_book,
                   const float* __restrict__ rot_book,
                   const float* __restrict__ trans_book,
                   float* __restrict__ out) {
    const int r   = blockIdx.x;
    const int tid = threadIdx.x;
    const int lane = tid & 31;
    const int wid  = tid >> 5;
    const __half* aux = g_gmax + ((size_t)p * BQ + r) * NGRPP;
    const uint4* row4 = g_s16v + (size_t)((size_t)p * BQ + r) * (NBP / 8);

    __shared__ __align__(16) unsigned int sbuf[1024];
    __shared__ unsigned int gsel[32];
    __shared__ int scand[NCAND];
    __shared__ float sval[NCAND];
    __shared__ int   sidx[NCAND];
    __shared__ unsigned int sT0, sTE;
    __shared__ int scnt, scnt2;

    const uint4* sb4 = reinterpret_cast<const uint4*>(sbuf);

    // ---- Phase A1: up to 7 group keys per thread (stride-256, coalesced)
    unsigned int gkey[7];
    unsigned int mybest = 0;
    #pragma unroll
    for (int k = 0; k < 7; k++) {
        int g = tid + (k << 8);
        unsigned int key = 0;
        if (g < NGRPP) {
            unsigned int hb = (unsigned int)__half_as_ushort(aux[g]);
            key = (h2ord(hb) << 16) | (0xFFFFu - (unsigned int)g);
        }
        gkey[k] = key;
        mybest = max(mybest, key);
    }

    sbuf[tid] = mybest;
    if (tid == 0) scnt = 0;
    __syncthreads();

    // exact rank of my thread-max among 256 (uint4 broadcast reads)
    {
        int rank = 0;
        #pragma unroll 8
        for (int i = 0; i < 64; i++) {
            uint4 v = sb4[i];
            rank += (v.x > mybest) + (v.y > mybest) + (v.z > mybest) + (v.w > mybest);
        }
        if (rank == 31) sT0 = mybest;
    }
    __syncthreads();
    const unsigned int T0 = sT0;

    // ---- Phase A2: survivors >= T0 (<= 224), counting-rank
    sbuf[tid] = 0;
    __syncthreads();
    #pragma unroll
    for (int k = 0; k < 7; k++)
        if (gkey[k] >= T0) sbuf[atomicAdd(&scnt, 1)] = gkey[k];
    __syncthreads();
    const int m = scnt;
    {
        unsigned int mk = sbuf[tid];
        int rk = 0;
        int mi4 = (m + 3) >> 2;
        #pragma unroll 4
        for (int i = 0; i < mi4; i++) {
            uint4 v = sb4[i];
            rk += (v.x > mk) + (v.y > mk) + (v.z > mk) + (v.w > mk);
        }
        if (tid < m) {
            if (rk < 32) gsel[rk] = mk;
            if (rk == 31) sTE = mk & 0xFFFF0000u;
        }
    }
    if (tid == 0) scnt2 = 0;
    __syncthreads();

    // ---- Phase B: gather 32 groups x 32 scores with fused threshold
    const unsigned int TE = sTE;
    sbuf[tid] = 0; sbuf[tid + 256] = 0; sbuf[tid + 512] = 0; sbuf[tid + 768] = 0;
    __syncthreads();
    if (tid < 128) {
        int g   = (int)(0xFFFFu - (gsel[tid >> 2] & 0xFFFFu));
        int sub = tid & 3;
        uint4 v = row4[g * 4 + sub];
        unsigned int w[4] = {v.x, v.y, v.z, v.w};
        int nb = g * 32 + sub * 8;
        #pragma unroll
        for (int e = 0; e < 4; e++) {
            unsigned int lo = w[e] & 0xFFFFu;
            unsigned int hi = w[e] >> 16;
            unsigned int k0 = (h2ord(lo) << 16) | (0xFFFFu - (unsigned int)(nb + 2 * e));
            unsigned int k1 = (h2ord(hi) << 16) | (0xFFFFu - (unsigned int)(nb + 2 * e + 1));
            if (k0 >= TE) sbuf[atomicAdd(&scnt2, 1)] = k0;
            if (k1 >= TE) sbuf[atomicAdd(&scnt2, 1)] = k1;
        }
    }
    __syncthreads();
    const int m2 = scnt2;
    {
        int mi4 = (m2 + 3) >> 2;
        for (int s = tid; s < m2; s += 256) {
            unsigned int kk = sbuf[s];
            int rk = 0;
            #pragma unroll 4
            for (int i = 0; i < mi4; i++) {
                uint4 v = sb4[i];
                rk += (v.x > kk) + (v.y > kk) + (v.z > kk) + (v.w > kk);
            }
            if (rk < 32) scand[rk] = (int)(0xFFFFu - (kk & 0xFFFFu));
        }
    }
    __syncthreads();

    // ---- exact refine: 32 fp32 dots over the candidates
    float4 a = reinterpret_cast<const float4*>(g_qf + (size_t)(p * BQ + r) * DIM)[lane];
    const float zq = (p == 1) ? g_zq[r] : 0.0f;
    const float* Bsrc = (p == 0) ? z_rot_book : z_trans_book;

    #pragma unroll
    for (int t = 0; t < NCAND / 8; t++) {
        int slot = wid * (NCAND / 8) + t;
        int ci = scand[slot];
        float4 b = reinterpret_cast<const float4*>(Bsrc + (size_t)ci * DIM)[lane];
        float sdot = a.x * b.x + a.y * b.y + a.z * b.z + a.w * b.w;
        #pragma unroll
        for (int o = 16; o; o >>= 1) sdot += __shfl_xor_sync(0xFFFFFFFFu, sdot, o);
        if (lane == 0) {
            sval[slot] = sdot - zq - ((p == 1) ? g_bq[ci] : 0.0f);
            sidx[slot] = ci;
        }
    }
    __syncthreads();

    if (wid == 0) {
        float v = sval[lane];
        int  ix = sidx[lane];
        const size_t BK = (size_t)BQ * TOPK;

        #pragma unroll
        for (int k = 0; k < TOPK; k++) {
            float bv = v; int bi = ix; int bl = lane;
            #pragma unroll
            for (int o = 16; o; o >>= 1) {
                float ov = __shfl_xor_sync(0xFFFFFFFFu, bv, o);
                int   oi = __shfl_xor_sync(0xFFFFFFFFu, bi, o);
                int   ol = __shfl_xor_sync(0xFFFFFFFFu, bl, o);
                if (ov > bv || (ov == bv && oi < bi)) { bv = ov; bi = oi; bl = ol; }
            }
            if (lane == bl) { v = -FLT_MAX; ix = 0x7FFFFFFF; }
            if (lane == 0) {
                size_t rk = (size_t)r * TOPK + k;
                if (p == 0) {
                    out[rk]          = bv;
                    out[BK + rk]     = (float)bi;
                    out[2 * BK + rk] = rot_book[bi];
                } else {
                    out[3 * BK + rk] = bv;
                    out[4 * BK + rk] = (float)bi;
                    out[5 * BK + rk * 3 + 0] = trans_book[(size_t)bi * 3 + 0];
                    out[5 * BK + rk * 3 + 1] = trans_book[(size_t)bi * 3 + 1];
                    out[5 * BK + rk * 3 + 2] = trans_book[(size_t)bi * 3 + 2];
                }
            }
        }
    }
}

// ======================= launch ============================================
extern "C" void kernel_launch(void* const* d_in, const int* in_sizes, int n_in,
                              void* d_out, int out_size) {
    const float* z_rot        = (const float*)d_in[0];
    const float* z_trans      = (const float*)d_in[1];
    const float* z_rot_book   = (const float*)d_in[2];
    const float* z_trans_book = (const float*)d_in[3];
    const float* rot_book     = (const float*)d_in[4];
    const float* trans_book   = (const float*)d_in[5];
    float* out = (float*)d_out;

    static cudaStream_t s2 = nullptr;
    static cudaEvent_t evFork = nullptr, evBooks = nullptr, evG0 = nullptr, evC0 = nullptr;
    static bool attr = false;
    if (!s2) {
        cudaStreamCreateWithFlags(&s2, cudaStreamNonBlocking);
        cudaEventCreateWithFlags(&evFork,  cudaEventDisableTiming);
        cudaEventCreateWithFlags(&evBooks, cudaEventDisableTiming);
        cudaEventCreateWithFlags(&evG0,    cudaEventDisableTiming);
        cudaEventCreateWithFlags(&evC0,    cudaEventDisableTiming);
    }
    if (!attr) {
        cudaFuncSetAttribute(score_hmma1, cudaFuncAttributeMaxDynamicSharedMemorySize, SMEM_GEMM);
        attr = true;
    }

    cudaEventRecord(evFork, 0);
    cudaStreamWaitEvent(s2, evFork, 0);

    prep_books<<<(NBP + 7) / 8, 256, 0, s2>>>(z_rot_book, z_trans_book);
    cudaEventRecord(evBooks, s2);
    prep_queries<<<BQ / 8, 256>>>(z_rot, z_trans);
    cudaStreamWaitEvent(0, evBooks, 0);

    dim3 ggrid(NBP / 128, BQ / 256);
    score_hmma1<<<ggrid, 256, SMEM_GEMM>>>(0);
    cudaEventRecord(evG0, 0);

    score_hmma1<<<ggrid, 256, SMEM_GEMM>>>(1);
    cudaStreamWaitEvent(s2, evG0, 0);
    cand_refine_kernel<<<BQ, 256, 0, s2>>>(0, z_rot_book, z_trans_book,
                                           rot_book, trans_book, out);
    cudaEventRecord(evC0, s2);

    cand_refine_kernel<<<BQ, 256>>>(1, z_rot_book, z_trans_book,
                                    rot_book, trans_book, out);
    cudaStreamWaitEvent(0, evC0, 0);
}